// round 8
// baseline (speedup 1.0000x reference)
#include <cuda_runtime.h>
#include <cuda_bf16.h>
#include <math.h>

// Problem constants
#define NB 2
#define EE 16
#define CC 16
#define VV (64*128*128)              // 1,048,576 voxels per batch

#define P1_TPB 256
#define P1_ITERS 16                  // float4 loads per thread
#define P1_BX (VV / (P1_TPB * P1_ITERS * 4))   // 64 blocks in x

#define P2_THREADS 256
#define P2_GX (VV / (P2_THREADS*4))  // 1024 blocks in x (one float4 per thread)
#define P2_TOTAL (P2_GX * NB)        // total pass2 blocks (ticket target)

#define DELTA_VAR 0.5f
#define DELTA_DIST 1.5f

// Scratch (device globals; zero-initialized at load; the fused finalize
// re-zeros them after consuming, so every call sees zeros -> deterministic).
__device__ float g_sums[NB][CC][EE];
__device__ float g_counts[NB][CC];
__device__ float g_var[NB][CC];
__device__ unsigned int g_ticket;

// ---------------------------------------------------------------------------
// Pass 1: per-cluster sums via REGISTER select-accumulation (no smem RMW, no
// chains). Block = (16K-voxel slab, plane e, batch n). Each thread: 16 fp32
// accumulators; per element 16x (ISETP + predicated FADD), all independent.
// Loads: paired float4(x)/int4(t), software-pipelined 2 iters ahead (MLP=4).
// t re-read per plane stays L2-resident (8.4MB << L2).
// e==0 blocks also accumulate counts via ballot+popc (packed 2x16-bit).
// ---------------------------------------------------------------------------
__global__ __launch_bounds__(P1_TPB, 4)
void pass1_kernel(const float* __restrict__ x, const int* __restrict__ t) {
    const int e   = blockIdx.y;
    const int n   = blockIdx.z;
    const int tid = threadIdx.x;

    const float4* xp = (const float4*)(x + ((size_t)n * EE + e) * VV)
                       + (size_t)blockIdx.x * (P1_TPB * P1_ITERS) + tid;
    const int4*   tp = (const int4*)(t + (size_t)n * VV)
                       + (size_t)blockIdx.x * (P1_TPB * P1_ITERS) + tid;

    float acc[CC];
    #pragma unroll
    for (int c = 0; c < CC; c++) acc[c] = 0.0f;

    const bool do_cnt = (e == 0);
    unsigned int cnt[8];
    #pragma unroll
    for (int c = 0; c < 8; c++) cnt[c] = 0u;

    // pipelined: hold 2 iterations in flight
    float4 xa = xp[0], xb = xp[P1_TPB];
    int4   ta = tp[0], tb = tp[P1_TPB];

    #pragma unroll
    for (int it = 0; it < P1_ITERS; it += 2) {
        float4 xa2, xb2; int4 ta2, tb2;
        if (it + 2 < P1_ITERS) {
            xa2 = xp[(it + 2) * P1_TPB];
            xb2 = xp[(it + 3) * P1_TPB];
            ta2 = tp[(it + 2) * P1_TPB];
            tb2 = tp[(it + 3) * P1_TPB];
        }

        const float va[8] = {xa.x, xa.y, xa.z, xa.w, xb.x, xb.y, xb.z, xb.w};
        const int   la[8] = {ta.x, ta.y, ta.z, ta.w, tb.x, tb.y, tb.z, tb.w};

        #pragma unroll
        for (int k = 0; k < 8; k++) {
            const int   lab = la[k];
            const float v   = va[k];
            #pragma unroll
            for (int c = 0; c < CC; c++) {
                bool p = (lab == c);
                if (p) acc[c] += v;
                if (do_cnt) {
                    unsigned int m = __ballot_sync(0xffffffffu, p);
                    cnt[c >> 1] += (c & 1) ? ((unsigned)__popc(m) << 16)
                                           : (unsigned)__popc(m);
                }
            }
        }

        xa = xa2; xb = xb2; ta = ta2; tb = tb2;
    }

    // block reduction of sums: smem transpose then warp-per-2-clusters
    __shared__ float red[CC][P1_TPB];   // 16 KB
    #pragma unroll
    for (int c = 0; c < CC; c++) red[c][tid] = acc[c];
    __syncthreads();

    const int w = tid >> 5, lane = tid & 31;
    #pragma unroll
    for (int k = 0; k < 2; k++) {
        const int c = w * 2 + k;
        float s = 0.0f;
        #pragma unroll
        for (int j = 0; j < P1_TPB; j += 32) s += red[c][lane + j];
        #pragma unroll
        for (int o = 16; o > 0; o >>= 1) s += __shfl_xor_sync(0xffffffffu, s, o);
        if (lane == 0) atomicAdd(&g_sums[n][c][e], s);
    }

    // counts (e==0 blocks): cnt is warp-uniform (ballot-summed); lane 0 emits
    if (do_cnt && lane == 0) {
        #pragma unroll
        for (int c = 0; c < 8; c++) {
            atomicAdd(&g_counts[n][2 * c],     (float)(cnt[c] & 0xffffu));
            atomicAdd(&g_counts[n][2 * c + 1], (float)(cnt[c] >> 16));
        }
    }
}

// ---------------------------------------------------------------------------
// Pass 2: variance term, with finalize FUSED into the last-finishing block
// (ticket pattern). One float4 (4 voxels) per thread; 8 LDG.128 in flight per
// plane batch. Means in smem (stride 20). Traversal reversed for L2 reuse.
// ---------------------------------------------------------------------------
__global__ __launch_bounds__(P2_THREADS)
void pass2_kernel(const float* __restrict__ x, const int* __restrict__ t,
                  float* __restrict__ out) {
    __shared__ float means_s[CC * 20];      // padded stride 20
    __shared__ float vacc[8][CC * 32];      // 16 KB (8 warps)
    __shared__ float wpart[8][CC];
    __shared__ unsigned int s_ticket;

    const int n    = blockIdx.y;
    const int tid  = threadIdx.x;
    const int w    = tid >> 5;
    const int lane = tid & 31;

    if (tid < CC * EE) {
        int c = tid >> 4, e = tid & 15;
        means_s[c * 20 + e] = g_sums[n][c][e] / g_counts[n][c];
    }
    for (int i = tid; i < 8 * CC * 32; i += P2_THREADS) (&vacc[0][0])[i] = 0.0f;
    __syncthreads();

    // reversed bijective index -> 4 consecutive voxels, warp stays contiguous
    const int idx = (P2_GX * P2_THREADS - 1) - (blockIdx.x * P2_THREADS + tid);
    const int v   = idx * 4;

    const float* xb = x + (size_t)n * EE * VV;
    const int4 lb = *(const int4*)(t + (size_t)n * VV + v);

    float ss0 = 0.0f, ss1 = 0.0f, ss2 = 0.0f, ss3 = 0.0f;
    #pragma unroll
    for (int eo = 0; eo < EE; eo += 8) {
        float4 xv[8];
        #pragma unroll
        for (int e = 0; e < 8; e++)
            xv[e] = *(const float4*)(xb + (size_t)(eo + e) * VV + v);
        #pragma unroll
        for (int e = 0; e < 8; e++) {
            const int ee = eo + e;
            float d;
            d = xv[e].x - means_s[lb.x * 20 + ee]; ss0 = fmaf(d, d, ss0);
            d = xv[e].y - means_s[lb.y * 20 + ee]; ss1 = fmaf(d, d, ss1);
            d = xv[e].z - means_s[lb.z * 20 + ee]; ss2 = fmaf(d, d, ss2);
            d = xv[e].w - means_s[lb.w * 20 + ee]; ss3 = fmaf(d, d, ss3);
        }
    }

    float* myv = vacc[w];
    float h;
    h = fmaxf(sqrtf(ss0) - DELTA_VAR, 0.0f); myv[lb.x * 32 + lane] += h * h;
    h = fmaxf(sqrtf(ss1) - DELTA_VAR, 0.0f); myv[lb.y * 32 + lane] += h * h;
    h = fmaxf(sqrtf(ss2) - DELTA_VAR, 0.0f); myv[lb.z * 32 + lane] += h * h;
    h = fmaxf(sqrtf(ss3) - DELTA_VAR, 0.0f); myv[lb.w * 32 + lane] += h * h;
    __syncwarp();

    #pragma unroll
    for (int c = 0; c < CC; c++) {
        float vv = myv[c * 32 + lane];
        #pragma unroll
        for (int o = 16; o > 0; o >>= 1) vv += __shfl_xor_sync(0xffffffffu, vv, o);
        if (lane == 0) wpart[w][c] = vv;
    }
    __syncthreads();

    if (tid < CC) {
        float s = 0.0f;
        #pragma unroll
        for (int ww = 0; ww < 8; ww++) s += wpart[ww][tid];
        atomicAdd(&g_var[n][tid], s);
    }

    // ---- fused finalize: last block to finish does the tiny epilogue ----
    __threadfence();
    if (tid == 0) s_ticket = atomicAdd(&g_ticket, 1u);
    __syncthreads();
    if (s_ticket != P2_TOTAL - 1) return;
    __threadfence();   // make all blocks' g_var/g_sums/g_counts visible

    __shared__ float means_f[NB][CC][EE];   // 2 KB
    __shared__ float accf[NB][3];           // [n][0]=var, [1]=dist, [2]=reg

    if (tid < NB * 3) (&accf[0][0])[tid] = 0.0f;
    for (int i = tid; i < NB * CC * EE; i += P2_THREADS) {
        int nn = i >> 8, c = (i >> 4) & 15, e = i & 15;
        means_f[nn][c][e] = g_sums[nn][c][e] / g_counts[nn][c];
    }
    __syncthreads();

    if (tid < NB * CC) {   // variance + regularizer terms
        int nn = tid >> 4, c = tid & 15;
        atomicAdd(&accf[nn][0], g_var[nn][c] / g_counts[nn][c]);
        float s = 0.0f;
        #pragma unroll
        for (int e = 0; e < EE; e++) {
            float m = means_f[nn][c][e];
            s = fmaf(m, m, s);
        }
        atomicAdd(&accf[nn][2], sqrtf(s));
    }

    for (int i = tid; i < NB * CC * CC; i += P2_THREADS) {  // all-pairs repulsion
        int nn = i >> 8, a = (i >> 4) & 15, b = i & 15;
        float s = 0.0f;
        #pragma unroll
        for (int e = 0; e < EE; e++) {
            float d = means_f[nn][a][e] - means_f[nn][b][e];
            s = fmaf(d, d, s);
        }
        float dmat = sqrtf(s);
        float rep  = (a == b) ? 0.0f : (2.0f * DELTA_DIST);
        float hh   = fmaxf(rep - dmat, 0.0f);
        atomicAdd(&accf[nn][1], hh * hh);
    }
    __syncthreads();

    if (tid == 0) {
        float loss = 0.0f;
        #pragma unroll
        for (int nn = 0; nn < NB; nn++) {
            float var_term  = accf[nn][0] / (float)CC;
            float dist_term = accf[nn][1] / (float)(CC * (CC - 1));
            float reg_term  = accf[nn][2] / (float)CC;
            loss += var_term + dist_term + 0.001f * reg_term;
        }
        out[0] = loss / (float)NB;
        g_ticket = 0u;
    }
    __syncthreads();

    // re-zero scratch for the next (graph-replay) invocation
    {
        float* s = &g_sums[0][0][0];
        for (int i = tid; i < NB * CC * EE; i += P2_THREADS) s[i] = 0.0f;
        float* c = &g_counts[0][0];
        for (int i = tid; i < NB * CC; i += P2_THREADS) c[i] = 0.0f;
        float* vv = &g_var[0][0];
        for (int i = tid; i < NB * CC; i += P2_THREADS) vv[i] = 0.0f;
    }
}

// ---------------------------------------------------------------------------
extern "C" void kernel_launch(void* const* d_in, const int* in_sizes, int n_in,
                              void* d_out, int out_size) {
    const float* x = (const float*)d_in[0];   // [2,16,64,128,128] f32
    const int*   t = (const int*)d_in[1];     // [2,64,128,128]    i32
    float* out = (float*)d_out;

    pass1_kernel<<<dim3(P1_BX, EE, NB), P1_TPB>>>(x, t);
    pass2_kernel<<<dim3(P2_GX, NB), P2_THREADS>>>(x, t, out);
}

// round 9
// speedup vs baseline: 1.9225x; 1.9225x over previous
#include <cuda_runtime.h>
#include <cuda_bf16.h>
#include <math.h>

// Problem constants
#define NB 2
#define EE 16
#define CC 16
#define VV (64*128*128)              // 1,048,576 voxels per batch

#define CHUNK1 4096
#define P1_GX (VV / CHUNK1)          // 256 chunks
#define P1_ITERS (CHUNK1 / 128)      // 32 float4-iterations per lane

#define P2_THREADS 256
#define P2_GX (VV / (P2_THREADS*4))  // 1024 blocks in x (one float4 per thread)
#define P2_TOTAL (P2_GX * NB)        // total pass2 blocks (ticket target)

#define DELTA_VAR 0.5f
#define DELTA_DIST 1.5f

// Scratch (device globals; zero-initialized at load; the fused finalize
// re-zeros them after consuming, so every call sees zeros -> deterministic).
__device__ float g_sums[NB][CC][EE];
__device__ float g_counts[NB][CC];
__device__ float g_var[NB][CC];
__device__ unsigned int g_ticket;

// ---------------------------------------------------------------------------
// Pass 1: per-cluster sums + counts (smem slot-split, high-MLP).
// Block = chunk of 4096 voxels; 8 warps; warp w owns planes w and w+8 as two
// DISJOINT per-lane-column accumulator arrays (bank==lane, conflict-free).
// Labels LDG'd directly as int4 per warp (t is L2-resident; no staging, no
// extra sync). Depth-2 software pipeline -> 6 LDG.128 in flight per warp.
// Warp 0 additionally accumulates counts in a third disjoint array.
// smem: 16KB A + 16KB B + 2KB C = 34KB static -> 6 blocks/SM by smem.
// ---------------------------------------------------------------------------
__global__ __launch_bounds__(256)
void pass1_kernel(const float* __restrict__ x, const int* __restrict__ t) {
    __shared__ float accA[8][CC * 32];   // 16 KB  (plane w)
    __shared__ float accB[8][CC * 32];   // 16 KB  (plane w+8)
    __shared__ float accC[CC * 32];      // 2 KB   (counts, warp 0)

    const int n    = blockIdx.y;
    const int base = blockIdx.x * CHUNK1;
    const int tid  = threadIdx.x;
    const int w    = tid >> 5;
    const int lane = tid & 31;

    for (int i = tid; i < 8 * CC * 32; i += 256) {
        (&accA[0][0])[i] = 0.0f;
        (&accB[0][0])[i] = 0.0f;
    }
    for (int i = tid; i < CC * 32; i += 256) accC[i] = 0.0f;
    __syncthreads();

    float* A = accA[w];
    float* B = accB[w];
    const float* xpA = x + ((size_t)n * EE + w    ) * VV + base;
    const float* xpB = x + ((size_t)n * EE + w + 8) * VV + base;
    const int*   tp  = t + (size_t)n * VV + base;

    // depth-2 pipeline: slots 0/1, 6 LDG.128 outstanding
    int i = lane * 4;
    float4 va0 = *(const float4*)(xpA + i);
    float4 vb0 = *(const float4*)(xpB + i);
    int4   lb0 = *(const int4*)(tp + i);
    float4 va1 = *(const float4*)(xpA + i + 128);
    float4 vb1 = *(const float4*)(xpB + i + 128);
    int4   lb1 = *(const int4*)(tp + i + 128);

    if (w == 0) {
        #pragma unroll
        for (int it = 0; it < P1_ITERS; it++) {
            float4 va = (it & 1) ? va1 : va0;
            float4 vb = (it & 1) ? vb1 : vb0;
            int4   lb = (it & 1) ? lb1 : lb0;
            if (it + 2 < P1_ITERS) {
                const int off = i + 256;
                if (it & 1) {
                    va1 = *(const float4*)(xpA + off);
                    vb1 = *(const float4*)(xpB + off);
                    lb1 = *(const int4*)(tp + off);
                } else {
                    va0 = *(const float4*)(xpA + off);
                    vb0 = *(const float4*)(xpB + off);
                    lb0 = *(const int4*)(tp + off);
                }
            }
            A[lb.x * 32 + lane] += va.x;  B[lb.x * 32 + lane] += vb.x;  accC[lb.x * 32 + lane] += 1.0f;
            A[lb.y * 32 + lane] += va.y;  B[lb.y * 32 + lane] += vb.y;  accC[lb.y * 32 + lane] += 1.0f;
            A[lb.z * 32 + lane] += va.z;  B[lb.z * 32 + lane] += vb.z;  accC[lb.z * 32 + lane] += 1.0f;
            A[lb.w * 32 + lane] += va.w;  B[lb.w * 32 + lane] += vb.w;  accC[lb.w * 32 + lane] += 1.0f;
            i += 128;
        }
    } else {
        #pragma unroll
        for (int it = 0; it < P1_ITERS; it++) {
            float4 va = (it & 1) ? va1 : va0;
            float4 vb = (it & 1) ? vb1 : vb0;
            int4   lb = (it & 1) ? lb1 : lb0;
            if (it + 2 < P1_ITERS) {
                const int off = i + 256;
                if (it & 1) {
                    va1 = *(const float4*)(xpA + off);
                    vb1 = *(const float4*)(xpB + off);
                    lb1 = *(const int4*)(tp + off);
                } else {
                    va0 = *(const float4*)(xpA + off);
                    vb0 = *(const float4*)(xpB + off);
                    lb0 = *(const int4*)(tp + off);
                }
            }
            A[lb.x * 32 + lane] += va.x;  B[lb.x * 32 + lane] += vb.x;
            A[lb.y * 32 + lane] += va.y;  B[lb.y * 32 + lane] += vb.y;
            A[lb.z * 32 + lane] += va.z;  B[lb.z * 32 + lane] += vb.z;
            A[lb.w * 32 + lane] += va.w;  B[lb.w * 32 + lane] += vb.w;
            i += 128;
        }
    }
    __syncwarp();

    #pragma unroll
    for (int c = 0; c < CC; c++) {
        float sA = A[c * 32 + lane];
        float sB = B[c * 32 + lane];
        #pragma unroll
        for (int o = 16; o > 0; o >>= 1) {
            sA += __shfl_xor_sync(0xffffffffu, sA, o);
            sB += __shfl_xor_sync(0xffffffffu, sB, o);
        }
        if (lane == 0) {
            atomicAdd(&g_sums[n][c][w],     sA);
            atomicAdd(&g_sums[n][c][w + 8], sB);
        }
        if (w == 0) {
            float sC = accC[c * 32 + lane];
            #pragma unroll
            for (int o = 16; o > 0; o >>= 1) sC += __shfl_xor_sync(0xffffffffu, sC, o);
            if (lane == 0) atomicAdd(&g_counts[n][c], sC);
        }
    }
}

// ---------------------------------------------------------------------------
// Pass 2: variance term, with finalize FUSED into the last-finishing block
// (ticket pattern). One float4 (4 voxels) per thread; 8 LDG.128 in flight per
// plane batch. Means in smem (stride 20). Traversal reversed for L2 reuse.
// (Unchanged from the measured 55.4us version.)
// ---------------------------------------------------------------------------
__global__ __launch_bounds__(P2_THREADS)
void pass2_kernel(const float* __restrict__ x, const int* __restrict__ t,
                  float* __restrict__ out) {
    __shared__ float means_s[CC * 20];      // padded stride 20
    __shared__ float vacc[8][CC * 32];      // 16 KB (8 warps)
    __shared__ float wpart[8][CC];
    __shared__ unsigned int s_ticket;

    const int n    = blockIdx.y;
    const int tid  = threadIdx.x;
    const int w    = tid >> 5;
    const int lane = tid & 31;

    if (tid < CC * EE) {
        int c = tid >> 4, e = tid & 15;
        means_s[c * 20 + e] = g_sums[n][c][e] / g_counts[n][c];
    }
    for (int i = tid; i < 8 * CC * 32; i += P2_THREADS) (&vacc[0][0])[i] = 0.0f;
    __syncthreads();

    // reversed bijective index -> 4 consecutive voxels, warp stays contiguous
    const int idx = (P2_GX * P2_THREADS - 1) - (blockIdx.x * P2_THREADS + tid);
    const int v   = idx * 4;

    const float* xb = x + (size_t)n * EE * VV;
    const int4 lb = *(const int4*)(t + (size_t)n * VV + v);

    float ss0 = 0.0f, ss1 = 0.0f, ss2 = 0.0f, ss3 = 0.0f;
    #pragma unroll
    for (int eo = 0; eo < EE; eo += 8) {
        float4 xv[8];
        #pragma unroll
        for (int e = 0; e < 8; e++)
            xv[e] = *(const float4*)(xb + (size_t)(eo + e) * VV + v);
        #pragma unroll
        for (int e = 0; e < 8; e++) {
            const int ee = eo + e;
            float d;
            d = xv[e].x - means_s[lb.x * 20 + ee]; ss0 = fmaf(d, d, ss0);
            d = xv[e].y - means_s[lb.y * 20 + ee]; ss1 = fmaf(d, d, ss1);
            d = xv[e].z - means_s[lb.z * 20 + ee]; ss2 = fmaf(d, d, ss2);
            d = xv[e].w - means_s[lb.w * 20 + ee]; ss3 = fmaf(d, d, ss3);
        }
    }

    float* myv = vacc[w];
    float h;
    h = fmaxf(sqrtf(ss0) - DELTA_VAR, 0.0f); myv[lb.x * 32 + lane] += h * h;
    h = fmaxf(sqrtf(ss1) - DELTA_VAR, 0.0f); myv[lb.y * 32 + lane] += h * h;
    h = fmaxf(sqrtf(ss2) - DELTA_VAR, 0.0f); myv[lb.z * 32 + lane] += h * h;
    h = fmaxf(sqrtf(ss3) - DELTA_VAR, 0.0f); myv[lb.w * 32 + lane] += h * h;
    __syncwarp();

    #pragma unroll
    for (int c = 0; c < CC; c++) {
        float vv = myv[c * 32 + lane];
        #pragma unroll
        for (int o = 16; o > 0; o >>= 1) vv += __shfl_xor_sync(0xffffffffu, vv, o);
        if (lane == 0) wpart[w][c] = vv;
    }
    __syncthreads();

    if (tid < CC) {
        float s = 0.0f;
        #pragma unroll
        for (int ww = 0; ww < 8; ww++) s += wpart[ww][tid];
        atomicAdd(&g_var[n][tid], s);
    }

    // ---- fused finalize: last block to finish does the tiny epilogue ----
    __threadfence();
    if (tid == 0) s_ticket = atomicAdd(&g_ticket, 1u);
    __syncthreads();
    if (s_ticket != P2_TOTAL - 1) return;
    __threadfence();   // make all blocks' g_var/g_sums/g_counts visible

    __shared__ float means_f[NB][CC][EE];   // 2 KB
    __shared__ float accf[NB][3];           // [n][0]=var, [1]=dist, [2]=reg

    if (tid < NB * 3) (&accf[0][0])[tid] = 0.0f;
    for (int i = tid; i < NB * CC * EE; i += P2_THREADS) {
        int nn = i >> 8, c = (i >> 4) & 15, e = i & 15;
        means_f[nn][c][e] = g_sums[nn][c][e] / g_counts[nn][c];
    }
    __syncthreads();

    if (tid < NB * CC) {   // variance + regularizer terms
        int nn = tid >> 4, c = tid & 15;
        atomicAdd(&accf[nn][0], g_var[nn][c] / g_counts[nn][c]);
        float s = 0.0f;
        #pragma unroll
        for (int e = 0; e < EE; e++) {
            float m = means_f[nn][c][e];
            s = fmaf(m, m, s);
        }
        atomicAdd(&accf[nn][2], sqrtf(s));
    }

    for (int i = tid; i < NB * CC * CC; i += P2_THREADS) {  // all-pairs repulsion
        int nn = i >> 8, a = (i >> 4) & 15, b = i & 15;
        float s = 0.0f;
        #pragma unroll
        for (int e = 0; e < EE; e++) {
            float d = means_f[nn][a][e] - means_f[nn][b][e];
            s = fmaf(d, d, s);
        }
        float dmat = sqrtf(s);
        float rep  = (a == b) ? 0.0f : (2.0f * DELTA_DIST);
        float hh   = fmaxf(rep - dmat, 0.0f);
        atomicAdd(&accf[nn][1], hh * hh);
    }
    __syncthreads();

    if (tid == 0) {
        float loss = 0.0f;
        #pragma unroll
        for (int nn = 0; nn < NB; nn++) {
            float var_term  = accf[nn][0] / (float)CC;
            float dist_term = accf[nn][1] / (float)(CC * (CC - 1));
            float reg_term  = accf[nn][2] / (float)CC;
            loss += var_term + dist_term + 0.001f * reg_term;
        }
        out[0] = loss / (float)NB;
        g_ticket = 0u;
    }
    __syncthreads();

    // re-zero scratch for the next (graph-replay) invocation
    {
        float* s = &g_sums[0][0][0];
        for (int i = tid; i < NB * CC * EE; i += P2_THREADS) s[i] = 0.0f;
        float* c = &g_counts[0][0];
        for (int i = tid; i < NB * CC; i += P2_THREADS) c[i] = 0.0f;
        float* vv = &g_var[0][0];
        for (int i = tid; i < NB * CC; i += P2_THREADS) vv[i] = 0.0f;
    }
}

// ---------------------------------------------------------------------------
extern "C" void kernel_launch(void* const* d_in, const int* in_sizes, int n_in,
                              void* d_out, int out_size) {
    const float* x = (const float*)d_in[0];   // [2,16,64,128,128] f32
    const int*   t = (const int*)d_in[1];     // [2,64,128,128]    i32
    float* out = (float*)d_out;

    pass1_kernel<<<dim3(P1_GX, NB), 256>>>(x, t);
    pass2_kernel<<<dim3(P2_GX, NB), P2_THREADS>>>(x, t, out);
}